// round 11
// baseline (speedup 1.0000x reference)
#include <cuda_runtime.h>
#include <cuda_fp16.h>
#include <mma.h>
#include <stdint.h>

using namespace nvcuda;

#define SEQ 2048
#define EMB 512
#define MTOT 4096
#define HD 64
#define QKSCALE 0.125f
#define L2E 1.4426950408889634f

// fp32 scratch — R1-validated layouts
__device__ float g_q[16*SEQ*HD];       // [b*8+h][s][d]
__device__ float g_k[16*SEQ*HD];
__device__ float g_v[16*SEQ*HD];
__device__ float g_attn[(size_t)MTOT*EMB];   // [b*s][h*64+d]

__device__ __forceinline__ uint32_t smem_u32(const void* p) {
    uint32_t a;
    asm("{ .reg .u64 t; cvta.to.shared.u64 t, %1; cvt.u32.u64 %0, t; }" : "=r"(a) : "l"(p));
    return a;
}
__device__ __forceinline__ void ldsm4(uint32_t* r, uint32_t a) {
    asm volatile("ldmatrix.sync.aligned.m8n8.x4.shared.b16 {%0,%1,%2,%3}, [%4];"
        : "=r"(r[0]), "=r"(r[1]), "=r"(r[2]), "=r"(r[3]) : "r"(a));
}
__device__ __forceinline__ void ldsm4t(uint32_t* r, uint32_t a) {
    asm volatile("ldmatrix.sync.aligned.m8n8.x4.trans.shared.b16 {%0,%1,%2,%3}, [%4];"
        : "=r"(r[0]), "=r"(r[1]), "=r"(r[2]), "=r"(r[3]) : "r"(a));
}
__device__ __forceinline__ void mma16816(float* d, const uint32_t* a, const uint32_t* b) {
    asm volatile("mma.sync.aligned.m16n8k16.row.col.f32.f16.f16.f32 "
        "{%0,%1,%2,%3}, {%4,%5,%6,%7}, {%8,%9}, {%0,%1,%2,%3};"
        : "+f"(d[0]), "+f"(d[1]), "+f"(d[2]), "+f"(d[3])
        : "r"(a[0]), "r"(a[1]), "r"(a[2]), "r"(a[3]), "r"(b[0]), "r"(b[1]));
}
__device__ __forceinline__ float fast_exp2(float x) {
    float r; asm("ex2.approx.ftz.f32 %0, %1;" : "=f"(r) : "f"(x)); return r;
}
__device__ __forceinline__ void split2h(float v, __half& h, __half& l) {
    h = __float2half_rn(v);
    l = __float2half_rn(v - __half2float(h));
}
__device__ __forceinline__ uint32_t pk2h(__half a, __half b) {
    return (uint32_t)__half_as_ushort(a) | ((uint32_t)__half_as_ushort(b) << 16);
}
__device__ __forceinline__ void split_store(__half* H, __half* L, int off, float4 v) {
    __half h0,l0,h1,l1,h2,l2,h3,l3;
    split2h(v.x,h0,l0); split2h(v.y,h1,l1); split2h(v.z,h2,l2); split2h(v.w,h3,l3);
    *(uint2*)(H+off) = make_uint2(pk2h(h0,h1), pk2h(h2,h3));
    *(uint2*)(L+off) = make_uint2(pk2h(l0,l1), pk2h(l2,l3));
}

// ------------------------------ GEMM (R6-proven, unchanged) -----------------
#define GSMEM 71680
template<int MODE>
__global__ __launch_bounds__(256)
void gemm_kernel(const float* __restrict__ A, const float* __restrict__ B,
                 float* __restrict__ outp, const float* __restrict__ bias, int Nst)
{
    extern __shared__ __align__(128) char sm[];
    __half* Ah = (__half*)sm;
    __half* Al = (__half*)(sm + 18432);
    __half* Bh = (__half*)(sm + 36864);
    __half* Bl = (__half*)(sm + 54272);
    float*  Csm = (float*)sm;

    const int tid = threadIdx.x, w = tid >> 5;
    const int wm = w & 3, wn = w >> 2;
    const int col0 = blockIdx.x * 128, row0 = blockIdx.y * 128;

    wmma::fragment<wmma::accumulator, 16, 16, 16, float> acc[2][4];
#pragma unroll
    for (int mt = 0; mt < 2; mt++)
#pragma unroll
        for (int nt = 0; nt < 4; nt++) wmma::fill_fragment(acc[mt][nt], 0.f);

    for (int c = 0; c < 8; c++) {
        if (c) __syncthreads();
#pragma unroll
        for (int i = 0; i < 8; i++) {
            int idx = i * 256 + tid;
            int row = idx >> 4, c4 = (idx & 15) * 4;
            float4 v = *(const float4*)(A + (size_t)(row0 + row) * EMB + c * 64 + c4);
            split_store(Ah, Al, row * 72 + c4, v);
        }
#pragma unroll
        for (int i = 0; i < 8; i++) {
            int idx = i * 256 + tid;
            int row = idx >> 5, c4 = (idx & 31) * 4;
            float4 v = *(const float4*)(B + (size_t)(c * 64 + row) * Nst + col0 + c4);
            split_store(Bh, Bl, row * 136 + c4, v);
        }
        __syncthreads();
#pragma unroll
        for (int k = 0; k < 4; k++) {
            wmma::fragment<wmma::matrix_a, 16, 16, 16, __half, wmma::row_major> ah[2], al[2];
#pragma unroll
            for (int mt = 0; mt < 2; mt++) {
                wmma::load_matrix_sync(ah[mt], Ah + (wm * 32 + mt * 16) * 72 + k * 16, 72);
                wmma::load_matrix_sync(al[mt], Al + (wm * 32 + mt * 16) * 72 + k * 16, 72);
            }
#pragma unroll
            for (int nt = 0; nt < 4; nt++) {
                wmma::fragment<wmma::matrix_b, 16, 16, 16, __half, wmma::row_major> bh, bl;
                wmma::load_matrix_sync(bh, Bh + (k * 16) * 136 + wn * 64 + nt * 16, 136);
                wmma::load_matrix_sync(bl, Bl + (k * 16) * 136 + wn * 64 + nt * 16, 136);
#pragma unroll
                for (int mt = 0; mt < 2; mt++) {
                    wmma::mma_sync(acc[mt][nt], ah[mt], bh, acc[mt][nt]);
                    wmma::mma_sync(acc[mt][nt], ah[mt], bl, acc[mt][nt]);
                    wmma::mma_sync(acc[mt][nt], al[mt], bh, acc[mt][nt]);
                }
            }
        }
    }
    __syncthreads();
#pragma unroll
    for (int mt = 0; mt < 2; mt++)
#pragma unroll
        for (int nt = 0; nt < 4; nt++)
            wmma::store_matrix_sync(Csm + (wm * 32 + mt * 16) * 132 + wn * 64 + nt * 16,
                                    acc[mt][nt], 132, wmma::mem_row_major);
    __syncthreads();

    const int row = tid >> 1, cb = (tid & 1) * 64;
    const int grow = row0 + row;
    if (MODE == 2) {
#pragma unroll
        for (int j = 0; j < 64; j += 4) {
            int gcol = col0 + cb + j;
            float4 o = *(float4*)&Csm[row * 132 + cb + j];
            o.x += __ldg(bias + gcol + 0);
            o.y += __ldg(bias + gcol + 1);
            o.z += __ldg(bias + gcol + 2);
            o.w += __ldg(bias + gcol + 3);
            *(float4*)(outp + (size_t)grow * EMB + gcol) = o;
        }
    } else {
        int gc0 = col0 + cb;
        int which = gc0 >> 9;
        int head  = (gc0 & 511) >> 6;
        int s = grow & 2047, bb = grow >> 11;
        float* dst = (which == 0) ? g_q : (which == 1) ? g_k : g_v;
        size_t base = (((size_t)(bb * 8 + head)) * SEQ + s) * HD;
#pragma unroll
        for (int j = 0; j < 64; j += 4)
            *(float4*)(dst + base + j) = *(float4*)&Csm[row * 132 + cb + j];
    }
}

// ---------------------------- attention (R4 in-register pipeline) -----------
// CTA per (qt: 128 q-rows, bh). 16 tiles of 128 keys. 8 warps: 4 q-quarters
// (wm) x 2 key-halves (wn). S computed via mma.sync into registers; exp,
// rowsum, and P repack (C-frag -> A-frag) all in registers — S and P never
// touch smem. V via ldmatrix.trans. Hi-only P (2-mma PV), split Q/K/V.
// smem: Qh 0, Ql 18432, Kh 36864, Kl 55296, Vh 73728, Vl 92160 (all 128x72h).
// obuf (fp32 128x64) overlays K region post-loop; sumbuf overlays V region.
#define AT_QL 18432
#define AT_KH 36864
#define AT_KL 55296
#define AT_VH 73728
#define AT_VL 92160
#define ASMEM 110592

__global__ __launch_bounds__(256) void attn_kernel() {
    extern __shared__ __align__(128) char sm[];
    const uint32_t smb = smem_u32(sm);
    __half* Qh = (__half*)sm;
    __half* Ql = (__half*)(sm + AT_QL);
    __half* Kh = (__half*)(sm + AT_KH);
    __half* Kl = (__half*)(sm + AT_KL);
    __half* Vh = (__half*)(sm + AT_VH);
    __half* Vl = (__half*)(sm + AT_VL);
    float*  obuf   = (float*)(sm + AT_KH);   // post-loop reuse
    float*  sumbuf = (float*)(sm + AT_VH);   // post-loop reuse

    const int tid = threadIdx.x, lane = tid & 31, w = tid >> 5;
    const int wm = w & 3, wn = w >> 2;
    const int g = lane >> 2, c2 = (lane & 3) * 2;
    const int qt = blockIdx.x, bh = blockIdx.y;
    const int b = bh >> 3, h = bh & 7;
    const size_t bhSD = (size_t)bh * SEQ * HD;

    // Q tile (128 x 64), scaled + split, stride 72 halves
#pragma unroll
    for (int i = 0; i < 8; i++) {
        int idx = i * 256 + tid;
        int row = idx >> 4, c4 = (idx & 15) * 4;
        float4 v = *(const float4*)(g_q + bhSD + (size_t)(qt * 128 + row) * HD + c4);
        v.x *= QKSCALE; v.y *= QKSCALE; v.z *= QKSCALE; v.w *= QKSCALE;
        split_store(Qh, Ql, row * 72 + c4, v);
    }

    float acc_o[2][8][4] = {};
    float lrun[2][2] = {};

    const uint32_t aQH = smb + (wm * 32 + (lane & 15)) * 144 + (lane >> 4) * 16;
    const uint32_t aQL = aQH + AT_QL;
    const uint32_t bKH = smb + AT_KH +
        (wn * 64 + (lane & 7) + ((lane >> 4) & 1) * 8) * 144 + ((lane >> 3) & 1) * 16;
    const uint32_t bKL = bKH + (AT_KL - AT_KH);
    const uint32_t bVH = smb + AT_VH +
        (wn * 64 + (lane & 7) + ((lane >> 3) & 1) * 8) * 144 + ((lane >> 4) & 1) * 16;
    const uint32_t bVL = bVH + (AT_VL - AT_VH);

    for (int t = 0; t < 16; t++) {
        __syncthreads();
        // K,V tiles (128 keys x 64 d), split
#pragma unroll
        for (int i = 0; i < 8; i++) {
            int idx = i * 256 + tid;
            int row = idx >> 4, c4 = (idx & 15) * 4;
            size_t gs = bhSD + (size_t)(t * 128 + row) * HD + c4;
            split_store(Kh, Kl, row * 72 + c4, *(const float4*)(g_k + gs));
            split_store(Vh, Vl, row * 72 + c4, *(const float4*)(g_v + gs));
        }
        __syncthreads();

        // S = Q K^T (warp: 32 q-rows x 64 keys), 3-mma split
        float accs[2][8][4] = {};
#pragma unroll
        for (int kt = 0; kt < 4; kt++) {
            uint32_t ah[2][4], al2[2][4], bh8[8][2], bl8[8][2];
#pragma unroll
            for (int mt = 0; mt < 2; mt++) {
                ldsm4(ah[mt],  aQH + mt * 2304 + kt * 32);
                ldsm4(al2[mt], aQL + mt * 2304 + kt * 32);
            }
#pragma unroll
            for (int np = 0; np < 4; np++) {
                uint32_t t4[4];
                ldsm4(t4, bKH + np * 2304 + kt * 32);
                bh8[np*2][0] = t4[0]; bh8[np*2][1] = t4[1];
                bh8[np*2+1][0] = t4[2]; bh8[np*2+1][1] = t4[3];
                ldsm4(t4, bKL + np * 2304 + kt * 32);
                bl8[np*2][0] = t4[0]; bl8[np*2][1] = t4[1];
                bl8[np*2+1][0] = t4[2]; bl8[np*2+1][1] = t4[3];
            }
#pragma unroll
            for (int mt = 0; mt < 2; mt++)
#pragma unroll
                for (int nt = 0; nt < 8; nt++) {
                    mma16816(accs[mt][nt], ah[mt],  bh8[nt]);
                    mma16816(accs[mt][nt], ah[mt],  bl8[nt]);
                    mma16816(accs[mt][nt], al2[mt], bh8[nt]);
                }
        }

        // per 16-key group j: exp + rowsum + P repack in regs, then PV mma
#pragma unroll
        for (int j = 0; j < 4; j++) {
            uint32_t pAh[2][4];
#pragma unroll
            for (int mt = 0; mt < 2; mt++) {
#pragma unroll
                for (int q = 0; q < 2; q++) {        // nt = 2j+q
                    float* cc = accs[mt][2*j + q];
#pragma unroll
                    for (int e = 0; e < 4; e++) {
                        float p = fast_exp2(cc[e] * L2E);
                        lrun[mt][e >> 1] += p;
                        cc[e] = p;
                    }
                    pAh[mt][q*2]   = pk2h(__float2half_rn(cc[0]), __float2half_rn(cc[1]));
                    pAh[mt][q*2+1] = pk2h(__float2half_rn(cc[2]), __float2half_rn(cc[3]));
                }
            }
            uint32_t vh8[8][2], vl8[8][2];
#pragma unroll
            for (int np = 0; np < 4; np++) {
                uint32_t t4[4];
                ldsm4t(t4, bVH + j * 2304 + np * 32);
                vh8[np*2][0] = t4[0]; vh8[np*2][1] = t4[1];
                vh8[np*2+1][0] = t4[2]; vh8[np*2+1][1] = t4[3];
                ldsm4t(t4, bVL + j * 2304 + np * 32);
                vl8[np*2][0] = t4[0]; vl8[np*2][1] = t4[1];
                vl8[np*2+1][0] = t4[2]; vl8[np*2+1][1] = t4[3];
            }
#pragma unroll
            for (int mt = 0; mt < 2; mt++)
#pragma unroll
                for (int nt = 0; nt < 8; nt++) {
                    mma16816(acc_o[mt][nt], pAh[mt], vh8[nt]);
                    mma16816(acc_o[mt][nt], pAh[mt], vl8[nt]);
                }
        }
    }
    __syncthreads();   // V/K reads done: obuf/sumbuf regions reusable

    // rowsum: reduce over the 4 lanes of each quad (same row, different cols)
#pragma unroll
    for (int mt = 0; mt < 2; mt++)
#pragma unroll
        for (int rh = 0; rh < 2; rh++) {
            float v = lrun[mt][rh];
            v += __shfl_xor_sync(0xffffffffu, v, 1);
            v += __shfl_xor_sync(0xffffffffu, v, 2);
            lrun[mt][rh] = v;
        }
    if ((lane & 3) == 0) {
#pragma unroll
        for (int mt = 0; mt < 2; mt++)
#pragma unroll
            for (int rh = 0; rh < 2; rh++)
                sumbuf[wn * 128 + wm * 32 + mt * 16 + g + rh * 8] = lrun[mt][rh];
    }
    if (wn == 1) {
#pragma unroll
        for (int mt = 0; mt < 2; mt++)
#pragma unroll
            for (int rh = 0; rh < 2; rh++)
#pragma unroll
                for (int nt = 0; nt < 8; nt++) {
                    float2 o = {acc_o[mt][nt][rh*2], acc_o[mt][nt][rh*2+1]};
                    *(float2*)&obuf[wm * 2048 + (mt*16 + g + rh*8) * 64 + nt*8 + c2] = o;
                }
    }
    __syncthreads();
    if (wn == 0) {
#pragma unroll
        for (int mt = 0; mt < 2; mt++)
#pragma unroll
            for (int rh = 0; rh < 2; rh++) {
                int row = wm * 32 + mt * 16 + g + rh * 8;
                float inv = 1.f / (sumbuf[row] + sumbuf[128 + row]);
                size_t base = (size_t)(b * SEQ + qt * 128 + row) * EMB + h * HD;
#pragma unroll
                for (int nt = 0; nt < 8; nt++) {
                    float2 p = *(float2*)&obuf[wm * 2048 + (mt*16 + g + rh*8) * 64 + nt*8 + c2];
                    float2 o;
                    o.x = (acc_o[mt][nt][rh*2+0] + p.x) * inv;
                    o.y = (acc_o[mt][nt][rh*2+1] + p.y) * inv;
                    *(float2*)(g_attn + base + nt*8 + c2) = o;
                }
            }
    }
}

// ------------------------------ launch --------------------------------------
extern "C" void kernel_launch(void* const* d_in, const int* in_sizes, int n_in,
                              void* d_out, int out_size)
{
    const float* x     = (const float*)d_in[0];
    const float* w_qkv = (const float*)d_in[1];
    const float* w_o   = (const float*)d_in[2];
    const float* b_o   = (const float*)d_in[3];
    float* out = (float*)d_out;

    float* attn_ptr = nullptr;
    cudaGetSymbolAddress((void**)&attn_ptr, g_attn);
    cudaFuncSetAttribute(gemm_kernel<1>, cudaFuncAttributeMaxDynamicSharedMemorySize, GSMEM);
    cudaFuncSetAttribute(gemm_kernel<2>, cudaFuncAttributeMaxDynamicSharedMemorySize, GSMEM);
    cudaFuncSetAttribute(attn_kernel,    cudaFuncAttributeMaxDynamicSharedMemorySize, ASMEM);

    gemm_kernel<1><<<dim3(12, 32), 256, GSMEM>>>(x, w_qkv, nullptr, nullptr, 3 * EMB);
    attn_kernel<<<dim3(16, 16), 256, ASMEM>>>();
    gemm_kernel<2><<<dim3(4, 32), 256, GSMEM>>>(attn_ptr, w_o, out, b_o, EMB);
}

// round 12
// speedup vs baseline: 1.0197x; 1.0197x over previous
#include <cuda_runtime.h>
#include <cuda_fp16.h>
#include <mma.h>
#include <stdint.h>

using namespace nvcuda;

#define SEQ 2048
#define EMB 512
#define MTOT 4096
#define HD 64
#define QKSCALE 0.125f
#define L2E 1.4426950408889634f

// fp32 scratch — R1-validated layouts
__device__ float g_q[16*SEQ*HD];       // [b*8+h][s][d]
__device__ float g_k[16*SEQ*HD];
__device__ float g_v[16*SEQ*HD];
__device__ float g_attn[(size_t)MTOT*EMB];   // [b*s][h*64+d]

__device__ __forceinline__ uint32_t smem_u32(const void* p) {
    uint32_t a;
    asm("{ .reg .u64 t; cvta.to.shared.u64 t, %1; cvt.u32.u64 %0, t; }" : "=r"(a) : "l"(p));
    return a;
}
__device__ __forceinline__ void ldsm4(uint32_t* r, uint32_t a) {
    asm volatile("ldmatrix.sync.aligned.m8n8.x4.shared.b16 {%0,%1,%2,%3}, [%4];"
        : "=r"(r[0]), "=r"(r[1]), "=r"(r[2]), "=r"(r[3]) : "r"(a));
}
__device__ __forceinline__ void ldsm4t(uint32_t* r, uint32_t a) {
    asm volatile("ldmatrix.sync.aligned.m8n8.x4.trans.shared.b16 {%0,%1,%2,%3}, [%4];"
        : "=r"(r[0]), "=r"(r[1]), "=r"(r[2]), "=r"(r[3]) : "r"(a));
}
__device__ __forceinline__ void mma16816(float* d, const uint32_t* a, const uint32_t* b) {
    asm volatile("mma.sync.aligned.m16n8k16.row.col.f32.f16.f16.f32 "
        "{%0,%1,%2,%3}, {%4,%5,%6,%7}, {%8,%9}, {%0,%1,%2,%3};"
        : "+f"(d[0]), "+f"(d[1]), "+f"(d[2]), "+f"(d[3])
        : "r"(a[0]), "r"(a[1]), "r"(a[2]), "r"(a[3]), "r"(b[0]), "r"(b[1]));
}
__device__ __forceinline__ float fast_exp2(float x) {
    float r; asm("ex2.approx.ftz.f32 %0, %1;" : "=f"(r) : "f"(x)); return r;
}
__device__ __forceinline__ void split2h(float v, __half& h, __half& l) {
    h = __float2half_rn(v);
    l = __float2half_rn(v - __half2float(h));
}
__device__ __forceinline__ uint32_t pk2h(__half a, __half b) {
    return (uint32_t)__half_as_ushort(a) | ((uint32_t)__half_as_ushort(b) << 16);
}
__device__ __forceinline__ void split_store(__half* H, __half* L, int off, float4 v) {
    __half h0,l0,h1,l1,h2,l2,h3,l3;
    split2h(v.x,h0,l0); split2h(v.y,h1,l1); split2h(v.z,h2,l2); split2h(v.w,h3,l3);
    *(uint2*)(H+off) = make_uint2(pk2h(h0,h1), pk2h(h2,h3));
    *(uint2*)(L+off) = make_uint2(pk2h(l0,l1), pk2h(l2,l3));
}

// ------------------------------ GEMM (R6-proven, unchanged) -----------------
#define GSMEM 71680
template<int MODE>
__global__ __launch_bounds__(256)
void gemm_kernel(const float* __restrict__ A, const float* __restrict__ B,
                 float* __restrict__ outp, const float* __restrict__ bias, int Nst)
{
    extern __shared__ __align__(128) char sm[];
    __half* Ah = (__half*)sm;
    __half* Al = (__half*)(sm + 18432);
    __half* Bh = (__half*)(sm + 36864);
    __half* Bl = (__half*)(sm + 54272);
    float*  Csm = (float*)sm;

    const int tid = threadIdx.x, w = tid >> 5;
    const int wm = w & 3, wn = w >> 2;
    const int col0 = blockIdx.x * 128, row0 = blockIdx.y * 128;

    wmma::fragment<wmma::accumulator, 16, 16, 16, float> acc[2][4];
#pragma unroll
    for (int mt = 0; mt < 2; mt++)
#pragma unroll
        for (int nt = 0; nt < 4; nt++) wmma::fill_fragment(acc[mt][nt], 0.f);

    for (int c = 0; c < 8; c++) {
        if (c) __syncthreads();
#pragma unroll
        for (int i = 0; i < 8; i++) {
            int idx = i * 256 + tid;
            int row = idx >> 4, c4 = (idx & 15) * 4;
            float4 v = *(const float4*)(A + (size_t)(row0 + row) * EMB + c * 64 + c4);
            split_store(Ah, Al, row * 72 + c4, v);
        }
#pragma unroll
        for (int i = 0; i < 8; i++) {
            int idx = i * 256 + tid;
            int row = idx >> 5, c4 = (idx & 31) * 4;
            float4 v = *(const float4*)(B + (size_t)(c * 64 + row) * Nst + col0 + c4);
            split_store(Bh, Bl, row * 136 + c4, v);
        }
        __syncthreads();
#pragma unroll
        for (int k = 0; k < 4; k++) {
            wmma::fragment<wmma::matrix_a, 16, 16, 16, __half, wmma::row_major> ah[2], al[2];
#pragma unroll
            for (int mt = 0; mt < 2; mt++) {
                wmma::load_matrix_sync(ah[mt], Ah + (wm * 32 + mt * 16) * 72 + k * 16, 72);
                wmma::load_matrix_sync(al[mt], Al + (wm * 32 + mt * 16) * 72 + k * 16, 72);
            }
#pragma unroll
            for (int nt = 0; nt < 4; nt++) {
                wmma::fragment<wmma::matrix_b, 16, 16, 16, __half, wmma::row_major> bh, bl;
                wmma::load_matrix_sync(bh, Bh + (k * 16) * 136 + wn * 64 + nt * 16, 136);
                wmma::load_matrix_sync(bl, Bl + (k * 16) * 136 + wn * 64 + nt * 16, 136);
#pragma unroll
                for (int mt = 0; mt < 2; mt++) {
                    wmma::mma_sync(acc[mt][nt], ah[mt], bh, acc[mt][nt]);
                    wmma::mma_sync(acc[mt][nt], ah[mt], bl, acc[mt][nt]);
                    wmma::mma_sync(acc[mt][nt], al[mt], bh, acc[mt][nt]);
                }
            }
        }
    }
    __syncthreads();
#pragma unroll
    for (int mt = 0; mt < 2; mt++)
#pragma unroll
        for (int nt = 0; nt < 4; nt++)
            wmma::store_matrix_sync(Csm + (wm * 32 + mt * 16) * 132 + wn * 64 + nt * 16,
                                    acc[mt][nt], 132, wmma::mem_row_major);
    __syncthreads();

    const int row = tid >> 1, cb = (tid & 1) * 64;
    const int grow = row0 + row;
    if (MODE == 2) {
#pragma unroll
        for (int j = 0; j < 64; j += 4) {
            int gcol = col0 + cb + j;
            float4 o = *(float4*)&Csm[row * 132 + cb + j];
            o.x += __ldg(bias + gcol + 0);
            o.y += __ldg(bias + gcol + 1);
            o.z += __ldg(bias + gcol + 2);
            o.w += __ldg(bias + gcol + 3);
            *(float4*)(outp + (size_t)grow * EMB + gcol) = o;
        }
    } else {
        int gc0 = col0 + cb;
        int which = gc0 >> 9;
        int head  = (gc0 & 511) >> 6;
        int s = grow & 2047, bb = grow >> 11;
        float* dst = (which == 0) ? g_q : (which == 1) ? g_k : g_v;
        size_t base = (((size_t)(bb * 8 + head)) * SEQ + s) * HD;
#pragma unroll
        for (int j = 0; j < 64; j += 4)
            *(float4*)(dst + base + j) = *(float4*)&Csm[row * 132 + cb + j];
    }
}

// ---------------------------- attention (R4 in-register pipeline) -----------
// CTA per (qt: 128 q-rows, bh). 16 tiles of 128 keys. 8 warps: 4 q-quarters
// (wm) x 2 key-halves (wn). S computed via mma.sync into registers; exp,
// rowsum, and P repack (C-frag -> A-frag) all in registers — S and P never
// touch smem. V via ldmatrix.trans. Hi-only P (2-mma PV), split Q/K/V.
// smem: Qh 0, Ql 18432, Kh 36864, Kl 55296, Vh 73728, Vl 92160 (all 128x72h).
// obuf (fp32 128x64) overlays K region post-loop; sumbuf overlays V region.
#define AT_QL 18432
#define AT_KH 36864
#define AT_KL 55296
#define AT_VH 73728
#define AT_VL 92160
#define ASMEM 110592

__global__ __launch_bounds__(256) void attn_kernel() {
    extern __shared__ __align__(128) char sm[];
    const uint32_t smb = smem_u32(sm);
    __half* Qh = (__half*)sm;
    __half* Ql = (__half*)(sm + AT_QL);
    __half* Kh = (__half*)(sm + AT_KH);
    __half* Kl = (__half*)(sm + AT_KL);
    __half* Vh = (__half*)(sm + AT_VH);
    __half* Vl = (__half*)(sm + AT_VL);
    float*  obuf   = (float*)(sm + AT_KH);   // post-loop reuse
    float*  sumbuf = (float*)(sm + AT_VH);   // post-loop reuse

    const int tid = threadIdx.x, lane = tid & 31, w = tid >> 5;
    const int wm = w & 3, wn = w >> 2;
    const int g = lane >> 2, c2 = (lane & 3) * 2;
    const int qt = blockIdx.x, bh = blockIdx.y;
    const int b = bh >> 3, h = bh & 7;
    const size_t bhSD = (size_t)bh * SEQ * HD;

    // Q tile (128 x 64), scaled + split, stride 72 halves
#pragma unroll
    for (int i = 0; i < 8; i++) {
        int idx = i * 256 + tid;
        int row = idx >> 4, c4 = (idx & 15) * 4;
        float4 v = *(const float4*)(g_q + bhSD + (size_t)(qt * 128 + row) * HD + c4);
        v.x *= QKSCALE; v.y *= QKSCALE; v.z *= QKSCALE; v.w *= QKSCALE;
        split_store(Qh, Ql, row * 72 + c4, v);
    }

    float acc_o[2][8][4] = {};
    float lrun[2][2] = {};

    const uint32_t aQH = smb + (wm * 32 + (lane & 15)) * 144 + (lane >> 4) * 16;
    const uint32_t aQL = aQH + AT_QL;
    const uint32_t bKH = smb + AT_KH +
        (wn * 64 + (lane & 7) + ((lane >> 4) & 1) * 8) * 144 + ((lane >> 3) & 1) * 16;
    const uint32_t bKL = bKH + (AT_KL - AT_KH);
    const uint32_t bVH = smb + AT_VH +
        (wn * 64 + (lane & 7) + ((lane >> 3) & 1) * 8) * 144 + ((lane >> 4) & 1) * 16;
    const uint32_t bVL = bVH + (AT_VL - AT_VH);

    for (int t = 0; t < 16; t++) {
        __syncthreads();
        // K,V tiles (128 keys x 64 d), split
#pragma unroll
        for (int i = 0; i < 8; i++) {
            int idx = i * 256 + tid;
            int row = idx >> 4, c4 = (idx & 15) * 4;
            size_t gs = bhSD + (size_t)(t * 128 + row) * HD + c4;
            split_store(Kh, Kl, row * 72 + c4, *(const float4*)(g_k + gs));
            split_store(Vh, Vl, row * 72 + c4, *(const float4*)(g_v + gs));
        }
        __syncthreads();

        // S = Q K^T (warp: 32 q-rows x 64 keys), 3-mma split
        float accs[2][8][4] = {};
#pragma unroll
        for (int kt = 0; kt < 4; kt++) {
            uint32_t ah[2][4], al2[2][4], bh8[8][2], bl8[8][2];
#pragma unroll
            for (int mt = 0; mt < 2; mt++) {
                ldsm4(ah[mt],  aQH + mt * 2304 + kt * 32);
                ldsm4(al2[mt], aQL + mt * 2304 + kt * 32);
            }
#pragma unroll
            for (int np = 0; np < 4; np++) {
                uint32_t t4[4];
                ldsm4(t4, bKH + np * 2304 + kt * 32);
                bh8[np*2][0] = t4[0]; bh8[np*2][1] = t4[1];
                bh8[np*2+1][0] = t4[2]; bh8[np*2+1][1] = t4[3];
                ldsm4(t4, bKL + np * 2304 + kt * 32);
                bl8[np*2][0] = t4[0]; bl8[np*2][1] = t4[1];
                bl8[np*2+1][0] = t4[2]; bl8[np*2+1][1] = t4[3];
            }
#pragma unroll
            for (int mt = 0; mt < 2; mt++)
#pragma unroll
                for (int nt = 0; nt < 8; nt++) {
                    mma16816(accs[mt][nt], ah[mt],  bh8[nt]);
                    mma16816(accs[mt][nt], ah[mt],  bl8[nt]);
                    mma16816(accs[mt][nt], al2[mt], bh8[nt]);
                }
        }

        // per 16-key group j: exp + rowsum + P repack in regs, then PV mma
#pragma unroll
        for (int j = 0; j < 4; j++) {
            uint32_t pAh[2][4];
#pragma unroll
            for (int mt = 0; mt < 2; mt++) {
#pragma unroll
                for (int q = 0; q < 2; q++) {        // nt = 2j+q
                    float* cc = accs[mt][2*j + q];
#pragma unroll
                    for (int e = 0; e < 4; e++) {
                        float p = fast_exp2(cc[e] * L2E);
                        lrun[mt][e >> 1] += p;
                        cc[e] = p;
                    }
                    pAh[mt][q*2]   = pk2h(__float2half_rn(cc[0]), __float2half_rn(cc[1]));
                    pAh[mt][q*2+1] = pk2h(__float2half_rn(cc[2]), __float2half_rn(cc[3]));
                }
            }
            uint32_t vh8[8][2], vl8[8][2];
#pragma unroll
            for (int np = 0; np < 4; np++) {
                uint32_t t4[4];
                ldsm4t(t4, bVH + j * 2304 + np * 32);
                vh8[np*2][0] = t4[0]; vh8[np*2][1] = t4[1];
                vh8[np*2+1][0] = t4[2]; vh8[np*2+1][1] = t4[3];
                ldsm4t(t4, bVL + j * 2304 + np * 32);
                vl8[np*2][0] = t4[0]; vl8[np*2][1] = t4[1];
                vl8[np*2+1][0] = t4[2]; vl8[np*2+1][1] = t4[3];
            }
#pragma unroll
            for (int mt = 0; mt < 2; mt++)
#pragma unroll
                for (int nt = 0; nt < 8; nt++) {
                    mma16816(acc_o[mt][nt], pAh[mt], vh8[nt]);
                    mma16816(acc_o[mt][nt], pAh[mt], vl8[nt]);
                }
        }
    }
    __syncthreads();   // V/K reads done: obuf/sumbuf regions reusable

    // rowsum: reduce over the 4 lanes of each quad (same row, different cols)
#pragma unroll
    for (int mt = 0; mt < 2; mt++)
#pragma unroll
        for (int rh = 0; rh < 2; rh++) {
            float v = lrun[mt][rh];
            v += __shfl_xor_sync(0xffffffffu, v, 1);
            v += __shfl_xor_sync(0xffffffffu, v, 2);
            lrun[mt][rh] = v;
        }
    if ((lane & 3) == 0) {
#pragma unroll
        for (int mt = 0; mt < 2; mt++)
#pragma unroll
            for (int rh = 0; rh < 2; rh++)
                sumbuf[wn * 128 + wm * 32 + mt * 16 + g + rh * 8] = lrun[mt][rh];
    }
    if (wn == 1) {
#pragma unroll
        for (int mt = 0; mt < 2; mt++)
#pragma unroll
            for (int rh = 0; rh < 2; rh++)
#pragma unroll
                for (int nt = 0; nt < 8; nt++) {
                    float2 o = {acc_o[mt][nt][rh*2], acc_o[mt][nt][rh*2+1]};
                    *(float2*)&obuf[wm * 2048 + (mt*16 + g + rh*8) * 64 + nt*8 + c2] = o;
                }
    }
    __syncthreads();
    if (wn == 0) {
#pragma unroll
        for (int mt = 0; mt < 2; mt++)
#pragma unroll
            for (int rh = 0; rh < 2; rh++) {
                int row = wm * 32 + mt * 16 + g + rh * 8;
                float inv = 1.f / (sumbuf[row] + sumbuf[128 + row]);
                size_t base = (size_t)(b * SEQ + qt * 128 + row) * EMB + h * HD;
#pragma unroll
                for (int nt = 0; nt < 8; nt++) {
                    float2 p = *(float2*)&obuf[wm * 2048 + (mt*16 + g + rh*8) * 64 + nt*8 + c2];
                    float2 o;
                    o.x = (acc_o[mt][nt][rh*2+0] + p.x) * inv;
                    o.y = (acc_o[mt][nt][rh*2+1] + p.y) * inv;
                    *(float2*)(g_attn + base + nt*8 + c2) = o;
                }
            }
    }
}

// ------------------------------ launch --------------------------------------
extern "C" void kernel_launch(void* const* d_in, const int* in_sizes, int n_in,
                              void* d_out, int out_size)
{
    const float* x     = (const float*)d_in[0];
    const float* w_qkv = (const float*)d_in[1];
    const float* w_o   = (const float*)d_in[2];
    const float* b_o   = (const float*)d_in[3];
    float* out = (float*)d_out;

    float* attn_ptr = nullptr;
    cudaGetSymbolAddress((void**)&attn_ptr, g_attn);
    cudaFuncSetAttribute(gemm_kernel<1>, cudaFuncAttributeMaxDynamicSharedMemorySize, GSMEM);
    cudaFuncSetAttribute(gemm_kernel<2>, cudaFuncAttributeMaxDynamicSharedMemorySize, GSMEM);
    cudaFuncSetAttribute(attn_kernel,    cudaFuncAttributeMaxDynamicSharedMemorySize, ASMEM);

    gemm_kernel<1><<<dim3(12, 32), 256, GSMEM>>>(x, w_qkv, nullptr, nullptr, 3 * EMB);
    attn_kernel<<<dim3(16, 16), 256, ASMEM>>>();
    gemm_kernel<2><<<dim3(4, 32), 256, GSMEM>>>(attn_ptr, w_o, out, b_o, EMB);
}

// round 13
// speedup vs baseline: 1.1710x; 1.1484x over previous
#include <cuda_runtime.h>
#include <cuda_fp16.h>
#include <mma.h>
#include <stdint.h>

using namespace nvcuda;

#define SEQ 2048
#define EMB 512
#define MTOT 4096
#define HD 64
#define QKSCALE 0.125f
#define L2E 1.4426950408889634f

// scratch: Q/K/V pre-split fp16 hi/lo (Q pre-scaled), attn output fp32
__device__ __align__(16) __half g_qh[16*SEQ*HD], g_ql[16*SEQ*HD];  // [b*8+h][s][d]
__device__ __align__(16) __half g_kh[16*SEQ*HD], g_kl[16*SEQ*HD];
__device__ __align__(16) __half g_vh[16*SEQ*HD], g_vl[16*SEQ*HD];
__device__ __align__(16) float  g_attn[(size_t)MTOT*EMB];          // [b*s][h*64+d]

__device__ __forceinline__ uint32_t smem_u32(const void* p) {
    uint32_t a;
    asm("{ .reg .u64 t; cvta.to.shared.u64 t, %1; cvt.u32.u64 %0, t; }" : "=r"(a) : "l"(p));
    return a;
}
__device__ __forceinline__ void ldsm4(uint32_t* r, uint32_t a) {
    asm volatile("ldmatrix.sync.aligned.m8n8.x4.shared.b16 {%0,%1,%2,%3}, [%4];"
        : "=r"(r[0]), "=r"(r[1]), "=r"(r[2]), "=r"(r[3]) : "r"(a));
}
__device__ __forceinline__ void ldsm4t(uint32_t* r, uint32_t a) {
    asm volatile("ldmatrix.sync.aligned.m8n8.x4.trans.shared.b16 {%0,%1,%2,%3}, [%4];"
        : "=r"(r[0]), "=r"(r[1]), "=r"(r[2]), "=r"(r[3]) : "r"(a));
}
__device__ __forceinline__ void mma16816(float* d, const uint32_t* a, const uint32_t* b) {
    asm volatile("mma.sync.aligned.m16n8k16.row.col.f32.f16.f16.f32 "
        "{%0,%1,%2,%3}, {%4,%5,%6,%7}, {%8,%9}, {%0,%1,%2,%3};"
        : "+f"(d[0]), "+f"(d[1]), "+f"(d[2]), "+f"(d[3])
        : "r"(a[0]), "r"(a[1]), "r"(a[2]), "r"(a[3]), "r"(b[0]), "r"(b[1]));
}
__device__ __forceinline__ float fast_exp2(float x) {
    float r; asm("ex2.approx.ftz.f32 %0, %1;" : "=f"(r) : "f"(x)); return r;
}
__device__ __forceinline__ void split2h(float v, __half& h, __half& l) {
    h = __float2half_rn(v);
    l = __float2half_rn(v - __half2float(h));
}
__device__ __forceinline__ uint32_t pk2h(__half a, __half b) {
    return (uint32_t)__half_as_ushort(a) | ((uint32_t)__half_as_ushort(b) << 16);
}
__device__ __forceinline__ void split_store(__half* H, __half* L, int off, float4 v) {
    __half h0,l0,h1,l1,h2,l2,h3,l3;
    split2h(v.x,h0,l0); split2h(v.y,h1,l1); split2h(v.z,h2,l2); split2h(v.w,h3,l3);
    *(uint2*)(H+off) = make_uint2(pk2h(h0,h1), pk2h(h2,h3));
    *(uint2*)(L+off) = make_uint2(pk2h(l0,l1), pk2h(l2,l3));
}

#define CPA(d, s)   asm volatile("cp.async.cg.shared.global [%0], [%1], 16;" :: "r"(d), "l"(s))
#define CP_COMMIT() asm volatile("cp.async.commit_group;" ::: "memory")
#define CP_WAIT1()  asm volatile("cp.async.wait_group 1;" ::: "memory")
#define CP_WAIT0()  asm volatile("cp.async.wait_group 0;" ::: "memory")

// ------------------------------ GEMM (R6-proven core) -----------------------
// MODE 1: QKV -> pre-split fp16 hi/lo scatter (Q scaled by QKSCALE, exact pow2).
// MODE 2: C = A@B + bias, fp32 out.
#define GSMEM 71680
template<int MODE>
__global__ __launch_bounds__(256)
void gemm_kernel(const float* __restrict__ A, const float* __restrict__ B,
                 float* __restrict__ outp, const float* __restrict__ bias, int Nst)
{
    extern __shared__ __align__(128) char sm[];
    __half* Ah = (__half*)sm;
    __half* Al = (__half*)(sm + 18432);
    __half* Bh = (__half*)(sm + 36864);
    __half* Bl = (__half*)(sm + 54272);
    float*  Csm = (float*)sm;

    const int tid = threadIdx.x, w = tid >> 5;
    const int wm = w & 3, wn = w >> 2;
    const int col0 = blockIdx.x * 128, row0 = blockIdx.y * 128;

    wmma::fragment<wmma::accumulator, 16, 16, 16, float> acc[2][4];
#pragma unroll
    for (int mt = 0; mt < 2; mt++)
#pragma unroll
        for (int nt = 0; nt < 4; nt++) wmma::fill_fragment(acc[mt][nt], 0.f);

    for (int c = 0; c < 8; c++) {
        if (c) __syncthreads();
#pragma unroll
        for (int i = 0; i < 8; i++) {
            int idx = i * 256 + tid;
            int row = idx >> 4, c4 = (idx & 15) * 4;
            float4 v = *(const float4*)(A + (size_t)(row0 + row) * EMB + c * 64 + c4);
            split_store(Ah, Al, row * 72 + c4, v);
        }
#pragma unroll
        for (int i = 0; i < 8; i++) {
            int idx = i * 256 + tid;
            int row = idx >> 5, c4 = (idx & 31) * 4;
            float4 v = *(const float4*)(B + (size_t)(c * 64 + row) * Nst + col0 + c4);
            split_store(Bh, Bl, row * 136 + c4, v);
        }
        __syncthreads();
#pragma unroll
        for (int k = 0; k < 4; k++) {
            wmma::fragment<wmma::matrix_a, 16, 16, 16, __half, wmma::row_major> ah[2], al[2];
#pragma unroll
            for (int mt = 0; mt < 2; mt++) {
                wmma::load_matrix_sync(ah[mt], Ah + (wm * 32 + mt * 16) * 72 + k * 16, 72);
                wmma::load_matrix_sync(al[mt], Al + (wm * 32 + mt * 16) * 72 + k * 16, 72);
            }
#pragma unroll
            for (int nt = 0; nt < 4; nt++) {
                wmma::fragment<wmma::matrix_b, 16, 16, 16, __half, wmma::row_major> bh, bl;
                wmma::load_matrix_sync(bh, Bh + (k * 16) * 136 + wn * 64 + nt * 16, 136);
                wmma::load_matrix_sync(bl, Bl + (k * 16) * 136 + wn * 64 + nt * 16, 136);
#pragma unroll
                for (int mt = 0; mt < 2; mt++) {
                    wmma::mma_sync(acc[mt][nt], ah[mt], bh, acc[mt][nt]);
                    wmma::mma_sync(acc[mt][nt], ah[mt], bl, acc[mt][nt]);
                    wmma::mma_sync(acc[mt][nt], al[mt], bh, acc[mt][nt]);
                }
            }
        }
    }
    __syncthreads();
#pragma unroll
    for (int mt = 0; mt < 2; mt++)
#pragma unroll
        for (int nt = 0; nt < 4; nt++)
            wmma::store_matrix_sync(Csm + (wm * 32 + mt * 16) * 132 + wn * 64 + nt * 16,
                                    acc[mt][nt], 132, wmma::mem_row_major);
    __syncthreads();

    const int row = tid >> 1, cb = (tid & 1) * 64;
    const int grow = row0 + row;
    if (MODE == 2) {
#pragma unroll
        for (int j = 0; j < 64; j += 4) {
            int gcol = col0 + cb + j;
            float4 o = *(float4*)&Csm[row * 132 + cb + j];
            o.x += __ldg(bias + gcol + 0);
            o.y += __ldg(bias + gcol + 1);
            o.z += __ldg(bias + gcol + 2);
            o.w += __ldg(bias + gcol + 3);
            *(float4*)(outp + (size_t)grow * EMB + gcol) = o;
        }
    } else {
        int gc0 = col0 + cb;                  // 64-aligned -> one head, d = j
        int which = gc0 >> 9;
        int head  = (gc0 & 511) >> 6;
        int s = grow & 2047, bb = grow >> 11;
        float scale = (which == 0) ? QKSCALE : 1.f;
        __half* dh = (which == 0) ? g_qh : (which == 1) ? g_kh : g_vh;
        __half* dl = (which == 0) ? g_ql : (which == 1) ? g_kl : g_vl;
        size_t base = (((size_t)(bb * 8 + head)) * SEQ + s) * HD;
#pragma unroll
        for (int j = 0; j < 64; j += 4) {
            float4 v = *(float4*)&Csm[row * 132 + cb + j];
            v.x *= scale; v.y *= scale; v.z *= scale; v.w *= scale;
            split_store(dh + base, dl + base, j, v);
        }
    }
}

// ---------------------------- attention -------------------------------------
// CTA per (qt: 128 q-rows, bh). 16 tiles of 128 keys. 8 warps: 4 q-quarters x
// 2 key-halves. In-register softmax (R12-proven). K/V pre-split fp16 arrive
// via cp.async into DOUBLE-BUFFERED smem — no register staging, no cvt work.
// smem: Qh 0, Ql 18432; buffers at 36864 + bf*73728 (Kh 0, Kl 18432,
// Vh 36864, Vl 55296 within buffer). obuf/sumbuf overlay buffer 0 post-loop.
#define ASMEM 184320

__global__ __launch_bounds__(256) void attn_kernel() {
    extern __shared__ __align__(128) char sm[];
    const uint32_t smb = smem_u32(sm);
    __half* Qh = (__half*)sm;
    __half* Ql = (__half*)(sm + 18432);
    float*  obuf   = (float*)(sm + 36864);    // post-loop reuse (32KB)
    float*  sumbuf = (float*)(sm + 69632);

    const int tid = threadIdx.x, lane = tid & 31, w = tid >> 5;
    const int wm = w & 3, wn = w >> 2;
    const int g = lane >> 2, c2 = (lane & 3) * 2;
    const int qt = blockIdx.x, bh = blockIdx.y;
    const int b = bh >> 3, h = bh & 7;
    const size_t bhSD = (size_t)bh * SEQ * HD;

    // Q tile (pre-scaled, pre-split): direct copies
    const size_t qbase = bhSD + (size_t)qt * 128 * HD;
#pragma unroll
    for (int i = 0; i < 4; i++) {
        int idx = i * 256 + tid;
        int row = idx >> 3, ch = (idx & 7) * 8;
        *(uint4*)(Qh + row * 72 + ch) = *(const uint4*)(g_qh + qbase + (size_t)row * HD + ch);
        *(uint4*)(Ql + row * 72 + ch) = *(const uint4*)(g_ql + qbase + (size_t)row * HD + ch);
    }

    const uint32_t kvb0 = smb + 36864;
#define ISSUE(t, bf) do { \
    size_t gbase = bhSD + (size_t)(t) * 128 * HD; \
    uint32_t sb = kvb0 + (bf) * 73728; \
    _Pragma("unroll") \
    for (int i = 0; i < 4; i++) { \
        int idx = i * 256 + tid; \
        int row = idx >> 3, ch = (idx & 7) * 8; \
        size_t go = gbase + (size_t)row * HD + ch; \
        uint32_t so = sb + row * 144 + ch * 2; \
        CPA(so,         g_kh + go); \
        CPA(so + 18432, g_kl + go); \
        CPA(so + 36864, g_vh + go); \
        CPA(so + 55296, g_vl + go); \
    } \
    CP_COMMIT(); \
} while (0)

    float acc_o[2][8][4] = {};
    float lrun[2][2] = {};

    const uint32_t aQH = smb + (wm * 32 + (lane & 15)) * 144 + (lane >> 4) * 16;
    const uint32_t aQL = aQH + 18432;
    const uint32_t bKHo = (wn * 64 + (lane & 7) + ((lane >> 4) & 1) * 8) * 144 + ((lane >> 3) & 1) * 16;
    const uint32_t bVHo = 36864 + (wn * 64 + (lane & 7) + ((lane >> 3) & 1) * 8) * 144 + ((lane >> 4) & 1) * 16;

    ISSUE(0, 0);

    for (int t = 0; t < 16; t++) {
        const int bf = t & 1;
        if (t < 15) { ISSUE(t + 1, bf ^ 1); CP_WAIT1(); }
        else        { CP_WAIT0(); }
        __syncthreads();          // tile t visible to all warps

        const uint32_t kb = kvb0 + bf * 73728;

        // S = Q K^T (warp: 32 q-rows x 64 keys), 3-mma split
        float accs[2][8][4] = {};
#pragma unroll
        for (int kt = 0; kt < 4; kt++) {
            uint32_t ah[2][4], al2[2][4], bh8[8][2], bl8[8][2];
#pragma unroll
            for (int mt = 0; mt < 2; mt++) {
                ldsm4(ah[mt],  aQH + mt * 2304 + kt * 32);
                ldsm4(al2[mt], aQL + mt * 2304 + kt * 32);
            }
#pragma unroll
            for (int np = 0; np < 4; np++) {
                uint32_t t4[4];
                ldsm4(t4, kb + bKHo + np * 2304 + kt * 32);
                bh8[np*2][0] = t4[0]; bh8[np*2][1] = t4[1];
                bh8[np*2+1][0] = t4[2]; bh8[np*2+1][1] = t4[3];
                ldsm4(t4, kb + 18432 + bKHo + np * 2304 + kt * 32);
                bl8[np*2][0] = t4[0]; bl8[np*2][1] = t4[1];
                bl8[np*2+1][0] = t4[2]; bl8[np*2+1][1] = t4[3];
            }
#pragma unroll
            for (int mt = 0; mt < 2; mt++)
#pragma unroll
                for (int nt = 0; nt < 8; nt++) {
                    mma16816(accs[mt][nt], ah[mt],  bh8[nt]);
                    mma16816(accs[mt][nt], ah[mt],  bl8[nt]);
                    mma16816(accs[mt][nt], al2[mt], bh8[nt]);
                }
        }

        // per 16-key group: exp + rowsum + P repack in regs, then PV mma
#pragma unroll
        for (int j = 0; j < 4; j++) {
            uint32_t pAh[2][4];
#pragma unroll
            for (int mt = 0; mt < 2; mt++) {
#pragma unroll
                for (int q = 0; q < 2; q++) {
                    float* cc = accs[mt][2*j + q];
#pragma unroll
                    for (int e = 0; e < 4; e++) {
                        float p = fast_exp2(cc[e] * L2E);
                        lrun[mt][e >> 1] += p;
                        cc[e] = p;
                    }
                    pAh[mt][q*2]   = pk2h(__float2half_rn(cc[0]), __float2half_rn(cc[1]));
                    pAh[mt][q*2+1] = pk2h(__float2half_rn(cc[2]), __float2half_rn(cc[3]));
                }
            }
            uint32_t vh8[8][2], vl8[8][2];
#pragma unroll
            for (int np = 0; np < 4; np++) {
                uint32_t t4[4];
                ldsm4t(t4, kb + bVHo + j * 2304 + np * 32);
                vh8[np*2][0] = t4[0]; vh8[np*2][1] = t4[1];
                vh8[np*2+1][0] = t4[2]; vh8[np*2+1][1] = t4[3];
                ldsm4t(t4, kb + 18432 + bVHo + j * 2304 + np * 32);
                vl8[np*2][0] = t4[0]; vl8[np*2][1] = t4[1];
                vl8[np*2+1][0] = t4[2]; vl8[np*2+1][1] = t4[3];
            }
#pragma unroll
            for (int mt = 0; mt < 2; mt++)
#pragma unroll
                for (int nt = 0; nt < 8; nt++) {
                    mma16816(acc_o[mt][nt], pAh[mt], vh8[nt]);
                    mma16816(acc_o[mt][nt], pAh[mt], vl8[nt]);
                }
        }
        __syncthreads();          // all reads of buffer bf done
    }

    // rowsum reduce (quad lanes), then cross key-half combine via smem
#pragma unroll
    for (int mt = 0; mt < 2; mt++)
#pragma unroll
        for (int rh = 0; rh < 2; rh++) {
            float v = lrun[mt][rh];
            v += __shfl_xor_sync(0xffffffffu, v, 1);
            v += __shfl_xor_sync(0xffffffffu, v, 2);
            lrun[mt][rh] = v;
        }
    if ((lane & 3) == 0) {
#pragma unroll
        for (int mt = 0; mt < 2; mt++)
#pragma unroll
            for (int rh = 0; rh < 2; rh++)
                sumbuf[wn * 128 + wm * 32 + mt * 16 + g + rh * 8] = lrun[mt][rh];
    }
    if (wn == 1) {
#pragma unroll
        for (int mt = 0; mt < 2; mt++)
#pragma unroll
            for (int rh = 0; rh < 2; rh++)
#pragma unroll
                for (int nt = 0; nt < 8; nt++) {
                    float2 o = {acc_o[mt][nt][rh*2], acc_o[mt][nt][rh*2+1]};
                    *(float2*)&obuf[wm * 2048 + (mt*16 + g + rh*8) * 64 + nt*8 + c2] = o;
                }
    }
    __syncthreads();
    if (wn == 0) {
#pragma unroll
        for (int mt = 0; mt < 2; mt++)
#pragma unroll
            for (int rh = 0; rh < 2; rh++) {
                int row = wm * 32 + mt * 16 + g + rh * 8;
                float inv = 1.f / (sumbuf[row] + sumbuf[128 + row]);
                size_t base = (size_t)(b * SEQ + qt * 128 + row) * EMB + h * HD;
#pragma unroll
                for (int nt = 0; nt < 8; nt++) {
                    float2 p = *(float2*)&obuf[wm * 2048 + (mt*16 + g + rh*8) * 64 + nt*8 + c2];
                    float2 o;
                    o.x = (acc_o[mt][nt][rh*2+0] + p.x) * inv;
                    o.y = (acc_o[mt][nt][rh*2+1] + p.y) * inv;
                    *(float2*)(g_attn + base + nt*8 + c2) = o;
                }
            }
    }
}

// ------------------------------ launch --------------------------------------
extern "C" void kernel_launch(void* const* d_in, const int* in_sizes, int n_in,
                              void* d_out, int out_size)
{
    const float* x     = (const float*)d_in[0];
    const float* w_qkv = (const float*)d_in[1];
    const float* w_o   = (const float*)d_in[2];
    const float* b_o   = (const float*)d_in[3];
    float* out = (float*)d_out;

    float* attn_ptr = nullptr;
    cudaGetSymbolAddress((void**)&attn_ptr, g_attn);
    cudaFuncSetAttribute(gemm_kernel<1>, cudaFuncAttributeMaxDynamicSharedMemorySize, GSMEM);
    cudaFuncSetAttribute(gemm_kernel<2>, cudaFuncAttributeMaxDynamicSharedMemorySize, GSMEM);
    cudaFuncSetAttribute(attn_kernel,    cudaFuncAttributeMaxDynamicSharedMemorySize, ASMEM);

    gemm_kernel<1><<<dim3(12, 32), 256, GSMEM>>>(x, w_qkv, nullptr, nullptr, 3 * EMB);
    attn_kernel<<<dim3(16, 16), 256, ASMEM>>>();
    gemm_kernel<2><<<dim3(4, 32), 256, GSMEM>>>(attn_ptr, w_o, out, b_o, EMB);
}